// round 6
// baseline (speedup 1.0000x reference)
#include <cuda_runtime.h>
#include <cstdint>

#define NTOK 262144
#define DF 128
#define CC 64
#define TILES 2048
#define GRID 152
#define NTHR 512

// ---- static device scratch (per-CTA partials) ----
__device__ float  g_Fpart[GRID * CC * DF];
__device__ int    g_cntpart[GRID * CC];
__device__ double g_f2part[GRID];
__device__ double g_s2part[32];

// ---- shared memory byte offsets ----
#define SM_A0    0          // float[128*132] feature tile buf 0 (67584 B)
#define SM_A1    67584      // float[128*132] feature tile buf 1
#define SM_STAGE 135168     // float[128*66] dist staging; ALIASES ctf at init (33792 B)
#define SM_FSUM  168960     // float[64*132] per-CTA class sums (33792 B)
#define SM_F2    202752     // float[128]
#define SM_C2    203264     // float[64]
#define SM_LBL   203520     // int[128]
#define SM_CNT   204032     // int[64]
#define SM_CNTT  204288     // int[64]
#define SM_LIST  204544     // u8[64*128]
#define SM_TOTAL 212736

__device__ __forceinline__ uint32_t smem_u32(const void* p) {
    uint32_t a;
    asm("{ .reg .u64 t; cvta.to.shared.u64 t, %1; cvt.u32.u64 %0, t; }" : "=r"(a) : "l"(p));
    return a;
}
__device__ __forceinline__ float tf32r(float x) {
    unsigned u;
    asm("cvt.rna.tf32.f32 %0, %1;" : "=r"(u) : "f"(x));
    return __uint_as_float(u);
}
__device__ __forceinline__ void mma_tf32(float* d, unsigned a0, unsigned a1,
                                         unsigned a2, unsigned a3,
                                         unsigned b0, unsigned b1) {
    asm volatile(
        "mma.sync.aligned.m16n8k8.row.col.f32.tf32.tf32.f32 "
        "{%0,%1,%2,%3}, {%4,%5,%6,%7}, {%8,%9}, {%0,%1,%2,%3};"
        : "+f"(d[0]), "+f"(d[1]), "+f"(d[2]), "+f"(d[3])
        : "r"(a0), "r"(a1), "r"(a2), "r"(a3), "r"(b0), "r"(b1));
}
#define CP16(dst, src)  asm volatile("cp.async.cg.shared.global [%0], [%1], 16;" :: "r"(dst), "l"(src))
#define CP_COMMIT()     asm volatile("cp.async.commit_group;" ::: "memory")
#define CP_WAIT1()      asm volatile("cp.async.wait_group 1;" ::: "memory")
#define CP_WAIT0()      asm volatile("cp.async.wait_group 0;" ::: "memory")

// ============================================================
__global__ void __launch_bounds__(NTHR, 1)
k_main(const float* __restrict__ feature, const int* __restrict__ label,
       const float* __restrict__ centers, float* __restrict__ out)
{
    extern __shared__ __align__(16) char sm[];
    float*         ctf     = (float*)(sm + SM_STAGE);   // init-time alias
    float*         stage   = (float*)(sm + SM_STAGE);
    float*         F_sm    = (float*)(sm + SM_FSUM);
    float*         f2_sm   = (float*)(sm + SM_F2);
    float*         c2_sm   = (float*)(sm + SM_C2);
    int*           lbl_sm  = (int*)(sm + SM_LBL);
    int*           cnt_sm  = (int*)(sm + SM_CNT);
    int*           cntt_sm = (int*)(sm + SM_CNTT);
    unsigned char* list_sm = (unsigned char*)(sm + SM_LIST);

    const int tid = threadIdx.x, bid = blockIdx.x;
    const int w = tid >> 5, l = tid & 31;
    const int lq = l >> 2, lr = l & 3;
    const int mbase = (w >> 2) * 32;            // 4 m-groups of 32 tokens
    const int nbase = (w & 3) * 16;             // 4 n-groups of 16 classes
    const uint32_t smb = smem_u32(sm);
    const uint32_t abase[2] = { smb + SM_A0, smb + SM_A1 };

    // ---- prologue: start streaming first tile ----
    {
        const int t0 = bid;
        const float* src = feature + (size_t)t0 * 128 * DF;
        #pragma unroll
        for (int it = 0; it < 8; it++) {
            int c = it * NTHR + tid;            // 16B chunk id, 0..4095
            int row = c >> 5, off = (c & 31) * 16;
            CP16(abase[0] + row * 528 + off, (const char*)src + row * 512 + off);
        }
        CP_COMMIT();
    }

    // ---- one-time init (ctf aliases stage; consumed before any stage use) ----
    for (int i = tid; i < CC * 132; i += NTHR) F_sm[i] = 0.f;
    for (int i = tid; i < CC * DF; i += NTHR) {
        int n = i >> 7, k = i & 127;
        ctf[n * 132 + k] = tf32r(centers[i]);
    }
    if (tid < CC) {
        float s = 0.f;
        for (int k = 0; k < DF; k++) { float c = centers[tid * DF + k]; s += c * c; }
        c2_sm[tid] = s;
        cntt_sm[tid] = 0;
    }
    __syncthreads();

    // ---- persistent B fragments: classes nbase..nbase+15, all K ----
    unsigned bfr[16][2][2];
    #pragma unroll
    for (int kc = 0; kc < 16; kc++)
        #pragma unroll
        for (int j = 0; j < 2; j++) {
            const float* cp = &ctf[(nbase + j * 8 + lq) * 132 + kc * 8 + lr];
            bfr[kc][j][0] = __float_as_uint(cp[0]);
            bfr[kc][j][1] = __float_as_uint(cp[4]);
        }
    __syncthreads();                             // ctf fully read; stage free

    double f2acc = 0.0;
    int idx = 0;

    for (int tile = bid; tile < TILES; tile += GRID) {
        const int base = tile * 128;
        float* atf = (float*)(sm + (idx ? SM_A1 : SM_A0));

        // ---- issue next tile's cp.async, then wait for current ----
        const int nxt = tile + GRID;
        if (nxt < TILES) {
            const float* src = feature + (size_t)nxt * 128 * DF;
            const uint32_t dst = abase[idx ^ 1];
            #pragma unroll
            for (int it = 0; it < 8; it++) {
                int c = it * NTHR + tid;
                int row = c >> 5, off = (c & 31) * 16;
                CP16(dst + row * 528 + off, (const char*)src + row * 512 + off);
            }
            CP_COMMIT();
            CP_WAIT1();
        } else {
            CP_WAIT0();
        }
        __syncthreads();                         // S1: tile data visible; stage reusable

        if (tid < 128)      lbl_sm[tid] = label[base + tid] & (CC - 1);
        else if (tid < 192) cnt_sm[tid - 128] = 0;

        // ---- f2 (exact) + tf32 round, in place ----
        #pragma unroll
        for (int it = 0; it < 8; it++) {
            const int tok = it * 16 + w;
            float4* p = (float4*)&atf[tok * 132 + l * 4];
            float4 f4 = *p;
            float s = f4.x * f4.x + f4.y * f4.y + f4.z * f4.z + f4.w * f4.w;
            #pragma unroll
            for (int o = 16; o; o >>= 1) s += __shfl_xor_sync(0xffffffffu, s, o);
            if (l == 0) f2_sm[tok] = s;
            f4.x = tf32r(f4.x); f4.y = tf32r(f4.y);
            f4.z = tf32r(f4.z); f4.w = tf32r(f4.w);
            *p = f4;
        }
        __syncthreads();                         // S2: converted tile + labels visible

        // ---- per-tile class row lists ----
        if (tid < 128) {
            int c = lbl_sm[tid];
            int pos = atomicAdd(&cnt_sm[c], 1);
            list_sm[c * 128 + pos] = (unsigned char)tid;
        }

        // ---- GEMM: 32 tokens x 16 classes per warp ----
        float acc[2][2][4];
        #pragma unroll
        for (int mi = 0; mi < 2; mi++)
            #pragma unroll
            for (int j = 0; j < 2; j++)
                #pragma unroll
                for (int e = 0; e < 4; e++) acc[mi][j][e] = 0.f;

        #pragma unroll
        for (int kc = 0; kc < 16; kc++) {
            #pragma unroll
            for (int mi = 0; mi < 2; mi++) {
                const float* ap = &atf[(mbase + mi * 16 + lq) * 132 + kc * 8 + lr];
                unsigned a0 = __float_as_uint(ap[0]);
                unsigned a2 = __float_as_uint(ap[4]);
                unsigned a1 = __float_as_uint(ap[8 * 132]);
                unsigned a3 = __float_as_uint(ap[8 * 132 + 4]);
                mma_tf32(acc[mi][0], a0, a1, a2, a3, bfr[kc][0][0], bfr[kc][0][1]);
                mma_tf32(acc[mi][1], a0, a1, a2, a3, bfr[kc][1][0], bfr[kc][1][1]);
            }
        }
        __syncthreads();                         // S3: lists complete

        // ---- phase 3: per-class feature sums (thread = class x d-eighth) ----
        {
            const int c = tid >> 3, q = tid & 7;
            const int n = cnt_sm[c];
            const unsigned char* lst = list_sm + c * 128;
            float s[16];
            #pragma unroll
            for (int dd = 0; dd < 16; dd++) s[dd] = 0.f;
            for (int i = 0; i < n; i++) {
                const float* fp = &atf[lst[i] * 132 + q * 16];
                #pragma unroll
                for (int p = 0; p < 4; p++) {
                    float4 v = *(const float4*)&fp[p * 4];
                    s[4 * p + 0] += v.x; s[4 * p + 1] += v.y;
                    s[4 * p + 2] += v.z; s[4 * p + 3] += v.w;
                }
            }
            float* Fp = F_sm + c * 132 + q * 16;
            #pragma unroll
            for (int dd = 0; dd < 16; dd++) Fp[dd] += s[dd];
        }
        if (tid < CC)  cntt_sm[tid] += cnt_sm[tid];
        if (tid < 128) f2acc += (double)f2_sm[tid];

        // ---- epilogue: dist = f2 + c2 - 2*dot -> stage (stride 66) ----
        #pragma unroll
        for (int mi = 0; mi < 2; mi++) {
            const int r0 = mbase + mi * 16 + lq;
            const float ft0 = f2_sm[r0], ft1 = f2_sm[r0 + 8];
            #pragma unroll
            for (int j = 0; j < 2; j++) {
                const int n0 = nbase + j * 8 + lr * 2;
                const float cA = c2_sm[n0], cB = c2_sm[n0 + 1];
                float2 v0, v1;
                v0.x = fmaf(-2.f, acc[mi][j][0], ft0 + cA);
                v0.y = fmaf(-2.f, acc[mi][j][1], ft0 + cB);
                v1.x = fmaf(-2.f, acc[mi][j][2], ft1 + cA);
                v1.y = fmaf(-2.f, acc[mi][j][3], ft1 + cB);
                *(float2*)&stage[r0 * 66 + n0] = v0;
                *(float2*)&stage[(r0 + 8) * 66 + n0] = v1;
            }
        }
        __syncthreads();                         // S4: stage ready

        // ---- flat aligned store: out + 8193 + tile*8192 ----
        float* gdst = out + 1 + CC * DF + (size_t)tile * 8192;
        if (tid < 4) {
            if (tid < 3) gdst[tid] = stage[tid];
            else         gdst[8191] = stage[127 * 66 + 63];
        }
        for (int qq = tid; qq < 2047; qq += NTHR) {
            const int j0 = 3 + 4 * qq;
            float4 v;
            v.x = stage[((j0 + 0) >> 6) * 66 + ((j0 + 0) & 63)];
            v.y = stage[((j0 + 1) >> 6) * 66 + ((j0 + 1) & 63)];
            v.z = stage[((j0 + 2) >> 6) * 66 + ((j0 + 2) & 63)];
            v.w = stage[((j0 + 3) >> 6) * 66 + ((j0 + 3) & 63)];
            *(float4*)(gdst + j0) = v;
        }
        idx ^= 1;
    }

    // ---- flush per-CTA partials (deterministic slots) ----
    __syncthreads();
    for (int i = tid; i < CC * DF; i += NTHR)
        g_Fpart[bid * CC * DF + i] = F_sm[(i >> 7) * 132 + (i & 127)];
    if (tid < CC) g_cntpart[bid * CC + tid] = cntt_sm[tid];
    {
        double* dred = (double*)(sm + SM_STAGE);
        dred[tid] = (tid < 128) ? f2acc : 0.0;
        __syncthreads();
        if (tid == 0) {
            double s0 = 0.0, s1 = 0.0, s2 = 0.0, s3 = 0.0;
            for (int i = 0; i < 128; i += 4) {
                s0 += dred[i]; s1 += dred[i + 1]; s2 += dred[i + 2]; s3 += dred[i + 3];
            }
            g_f2part[bid] = (s0 + s1) + (s2 + s3);
        }
    }
}

// ============================================================
__global__ void k_final1(const float* __restrict__ centers, float* __restrict__ out)
{
    __shared__ int cnti[CC];
    __shared__ double dsum[256];
    int tid = threadIdx.x;
    if (tid < CC) {
        int s0 = 0, s1 = 0, s2 = 0, s3 = 0, b = 0;
        for (; b + 4 <= GRID; b += 4) {
            s0 += g_cntpart[(b + 0) * CC + tid]; s1 += g_cntpart[(b + 1) * CC + tid];
            s2 += g_cntpart[(b + 2) * CC + tid]; s3 += g_cntpart[(b + 3) * CC + tid];
        }
        for (; b < GRID; b++) s0 += g_cntpart[b * CC + tid];
        cnti[tid] = s0 + s1 + s2 + s3;
    }
    __syncthreads();
    int i = blockIdx.x * 256 + tid;
    double F0 = 0.0, F1 = 0.0, F2 = 0.0, F3 = 0.0;
    int b = 0;
    for (; b + 4 <= GRID; b += 4) {
        F0 += (double)g_Fpart[(b + 0) * CC * DF + i];
        F1 += (double)g_Fpart[(b + 1) * CC * DF + i];
        F2 += (double)g_Fpart[(b + 2) * CC * DF + i];
        F3 += (double)g_Fpart[(b + 3) * CC * DF + i];
    }
    for (; b < GRID; b++) F0 += (double)g_Fpart[b * CC * DF + i];
    double F = (F0 + F1) + (F2 + F3);
    int c = i >> 7;
    double cen = (double)centers[i];
    int n = cnti[c]; int ncl = n > 0 ? n : 1;
    out[1 + i] = (float)(((double)n * cen - F) / (double)ncl);
    dsum[tid] = F * cen;
    __syncthreads();
    for (int off = 128; off; off >>= 1) {
        if (tid < off) dsum[tid] += dsum[tid + off];
        __syncthreads();
    }
    if (tid == 0) g_s2part[blockIdx.x] = dsum[0];
}

__global__ void k_final2(const float* __restrict__ centers, float* __restrict__ out)
{
    __shared__ double sred[64];
    int tid = threadIdx.x;
    double s3 = 0.0;
    if (tid < CC) {
        int n0 = 0, n1 = 0, b = 0;
        for (; b + 2 <= GRID; b += 2) {
            n0 += g_cntpart[(b + 0) * CC + tid];
            n1 += g_cntpart[(b + 1) * CC + tid];
        }
        for (; b < GRID; b++) n0 += g_cntpart[b * CC + tid];
        int n = n0 + n1;
        double c0 = 0.0, c1 = 0.0;
        for (int k = 0; k < DF; k += 2) {
            double va = (double)centers[tid * DF + k];
            double vb = (double)centers[tid * DF + k + 1];
            c0 += va * va; c1 += vb * vb;
        }
        s3 = (double)n * (c0 + c1);
    }
    sred[tid] = s3;
    __syncthreads();
    for (int off = 32; off; off >>= 1) {
        if (tid < off) sred[tid] += sred[tid + off];
        __syncthreads();
    }
    if (tid == 0) {
        double a0 = 0.0, a1 = 0.0, a2 = 0.0, a3 = 0.0;
        int b = 0;
        for (; b + 4 <= GRID; b += 4) {
            a0 += g_f2part[b]; a1 += g_f2part[b + 1];
            a2 += g_f2part[b + 2]; a3 += g_f2part[b + 3];
        }
        for (; b < GRID; b++) a0 += g_f2part[b];
        double s1 = (a0 + a1) + (a2 + a3);
        double s2 = 0.0;
        for (int i = 0; i < 32; i += 4)
            s2 += (g_s2part[i] + g_s2part[i + 1]) + (g_s2part[i + 2] + g_s2part[i + 3]);
        out[0] = (float)((s1 - 2.0 * s2 + sred[0]) / ((double)NTOK * (double)DF));
    }
}

// ============================================================
extern "C" void kernel_launch(void* const* d_in, const int* in_sizes, int n_in,
                              void* d_out, int out_size)
{
    const float* feature = (const float*)d_in[0];
    const int*   label   = (const int*)d_in[1];
    const float* centers = (const float*)d_in[2];
    float*       out     = (float*)d_out;

    cudaFuncSetAttribute(k_main, cudaFuncAttributeMaxDynamicSharedMemorySize, SM_TOTAL);
    k_main<<<GRID, NTHR, SM_TOTAL>>>(feature, label, centers, out);
    k_final1<<<32, 256>>>(centers, out);
    k_final2<<<1, 64>>>(centers, out);
}